// round 3
// baseline (speedup 1.0000x reference)
#include <cuda_runtime.h>

#define DIM 1024
#define NPAIRS 512          // adjacent-pair complex coefficients
#define ROWS_PER_BLK 8
#define THREADS 256         // 8 warps, one row per warp

// Fused kernel: per-block coefficient log-tree in smem + warp-per-row apply.
//
// Math: with base point 0 and c=1,
//   log_map(0,x) = atanh(||x||)/||x|| * x        (row scale s1)
//   butterfly    = per adjacent pair (2j,2j+1): multiply by
//                  W_j = prod_{l=1..9} (a_l[j>>(l-1)] - i*b_l[j>>(l-1)])
//                  (level-l params at offset 4096 - 2^(12-l); l=0 unused, bs<2)
//   exp_map(0,u) = tanh(||u||)/max(||u||,1e-8) * u
__global__ __launch_bounds__(THREADS) void hyper_butterfly_fused(
    const float* __restrict__ params,
    const float4* __restrict__ x,
    float4* __restrict__ out)
{
    __shared__ float2 bufA[256];
    __shared__ float2 bufB[NPAIRS];

    const int tid  = threadIdx.x;
    const int lane = tid & 31;
    const int wid  = tid >> 5;

    const size_t row  = (size_t)blockIdx.x * ROWS_PER_BLK + wid;
    const size_t base = row * (DIM / 4);

    // ---- front-batched row loads (MLP=8) ----
    float4 v[8];
#pragma unroll
    for (int i = 0; i < 8; ++i)
        v[i] = __ldg(x + base + lane + 32 * i);

    // ---- coefficient log-tree in smem (hides under the DRAM loads) ----
    // T_10 = identity; T_l[k] = (a_l[k] - i b_l[k]) * T_{l+1}[k>>1], k < 2^(10-l)
    if (tid == 0) bufA[0] = make_float2(1.0f, 0.0f);
    __syncthreads();

    float2* src = bufA;
    float2* dst = bufB;
    for (int l = 9; l >= 1; --l) {
        const int n   = 1 << (10 - l);
        const int off = 4096 - (1 << (12 - l));
        for (int k = tid; k < n; k += THREADS) {
            float  a = params[off + 2 * k];
            float  b = params[off + 2 * k + 1];
            float2 p = src[k >> 1];
            // (a - i b) * (p.x + i p.y)
            dst[k] = make_float2(a * p.x + b * p.y, a * p.y - b * p.x);
        }
        __syncthreads();
        float2* t = src; src = dst; dst = t;
    }
    // Final 512 coefficients are in src (== bufB after 9 swaps).
    const float4* W4 = (const float4*)src;   // float4 j = coefs for pairs 2j, 2j+1

    // ---- apply: sums + complex multiply (results overwrite v) ----
    float ss = 0.0f, ss2 = 0.0f;
#pragma unroll
    for (int i = 0; i < 8; ++i) {
        float4 vv = v[i];
        float4 w  = W4[lane + 32 * i];       // conflict-free LDS.128
        ss += vv.x * vv.x + vv.y * vv.y + vv.z * vv.z + vv.w * vv.w;
        float r0 = w.x * vv.x - w.y * vv.y;
        float r1 = w.y * vv.x + w.x * vv.y;
        float r2 = w.z * vv.z - w.w * vv.w;
        float r3 = w.w * vv.z + w.z * vv.w;
        ss2 += r0 * r0 + r1 * r1 + r2 * r2 + r3 * r3;
        v[i] = make_float4(r0, r1, r2, r3);
    }

    // ---- single warp reduction, two interleaved trees ----
#pragma unroll
    for (int o = 16; o; o >>= 1) {
        ss  += __shfl_xor_sync(0xFFFFFFFFu, ss,  o);
        ss2 += __shfl_xor_sync(0xFFFFFFFFu, ss2, o);
    }

    float n  = sqrtf(ss);
    float s1 = (n > 0.0f) ? (atanhf(n) / n) : 1.0f;      // log_map scale
    float vn = fmaxf(s1 * sqrtf(ss2), 1e-8f);            // ||u||
    float s  = s1 * (tanhf(vn) / vn);                    // total scale

    // ---- scaled coalesced stores ----
#pragma unroll
    for (int i = 0; i < 8; ++i)
        out[base + lane + 32 * i] =
            make_float4(s * v[i].x, s * v[i].y, s * v[i].z, s * v[i].w);
}

extern "C" void kernel_launch(void* const* d_in, const int* in_sizes, int n_in,
                              void* d_out, int out_size) {
    const float* xp = (const float*)d_in[0];
    const float* pp = (const float*)d_in[1];
    long long n0 = in_sizes[0], n1 = in_sizes[1];
    if (n0 < n1) { const float* tmp = xp; xp = pp; pp = tmp; long long ts = n0; n0 = n1; n1 = ts; }
    int rows = (int)(n0 / DIM);

    hyper_butterfly_fused<<<rows / ROWS_PER_BLK, THREADS>>>(
        pp, (const float4*)xp, (float4*)d_out);
}